// round 2
// baseline (speedup 1.0000x reference)
#include <cuda_runtime.h>
#include <cstddef>

#define NMAX 100000
#define EMAX 1600000

// ---------------- scratch (device globals; no allocations allowed) ----------
__device__ float d_g[NMAX * 128];       // dinv * (h @ W)
__device__ float d_h[NMAX * 128];       // aggregated output (pre-relu)
__device__ int   d_degc[NMAX];
__device__ int   d_fill[NMAX];
__device__ float d_dinv[NMAX];
__device__ int   d_rowptr[NMAX + 1];
__device__ int   d_bsums[1024];
__device__ int   d_cols[EMAX];
__device__ float d_cs128[128];
__device__ float d_cv128[128 * 128];
__device__ float d_cs64[64];
__device__ float d_cv64[64 * 64];

// ---------------- init -------------------------------------------------------
__global__ void zero_kernel(int n) {
    int i = blockIdx.x * blockDim.x + threadIdx.x;
    if (i < n) { d_degc[i] = 0; d_fill[i] = 0; }
    if (i < 128) d_cs128[i] = 0.f;
    if (i < 64)  d_cs64[i] = 0.f;
    if (i < 128 * 128) d_cv128[i] = 0.f;
    if (i < 64 * 64)   d_cv64[i] = 0.f;
}

__global__ void hist_kernel(const int* __restrict__ row, int* __restrict__ degc, int e) {
    int i = blockIdx.x * blockDim.x + threadIdx.x;
    if (i < e) atomicAdd(&degc[row[i]], 1);
}

__global__ void dinv_kernel(const int* __restrict__ degc, float* __restrict__ dinv, int n) {
    int i = blockIdx.x * blockDim.x + threadIdx.x;
    if (i < n) dinv[i] = rsqrtf((float)(degc[i] + 1));   // +1 self loop, always > 0
}

// ---------------- exclusive scan (rowptr) -----------------------------------
__global__ void scan_block_kernel(const int* __restrict__ cnt, int* __restrict__ excl,
                                  int* __restrict__ bsums, int n) {
    __shared__ int sh[1024];
    int tid = threadIdx.x;
    int i = blockIdx.x * 1024 + tid;
    int v = (i < n) ? cnt[i] : 0;
    sh[tid] = v; __syncthreads();
    for (int off = 1; off < 1024; off <<= 1) {
        int t = (tid >= off) ? sh[tid - off] : 0;
        __syncthreads();
        sh[tid] += t;
        __syncthreads();
    }
    if (i < n) excl[i] = sh[tid] - v;
    if (tid == 1023) bsums[blockIdx.x] = sh[tid];
}

__global__ void scan_sums_kernel(int* __restrict__ bsums, int nb) {
    __shared__ int sh[1024];
    int tid = threadIdx.x;
    int v = (tid < nb) ? bsums[tid] : 0;
    sh[tid] = v; __syncthreads();
    for (int off = 1; off < 1024; off <<= 1) {
        int t = (tid >= off) ? sh[tid - off] : 0;
        __syncthreads();
        sh[tid] += t;
        __syncthreads();
    }
    if (tid < nb) bsums[tid] = sh[tid] - v;   // exclusive
}

__global__ void scan_add_kernel(int* __restrict__ rowptr, const int* __restrict__ bsums,
                                int n, int e) {
    int i = blockIdx.x * 1024 + threadIdx.x;
    if (i < n) rowptr[i] += bsums[blockIdx.x];
    if (blockIdx.x == 0 && threadIdx.x == 0) rowptr[n] = e;
}

__global__ void scatter_kernel(const int* __restrict__ row, const int* __restrict__ col,
                               const int* __restrict__ rowptr, int* __restrict__ fill,
                               int* __restrict__ colsorted, int e) {
    int i = blockIdx.x * blockDim.x + threadIdx.x;
    if (i < e) {
        int r = row[i];
        int pos = rowptr[r] + atomicAdd(&fill[r], 1);
        colsorted[pos] = col[i];
    }
}

// ---------------- GEMM: out[r, :] = dinv[r] * (act(A[r,:]) @ W) --------------
template <int K, int M, bool RELU>
__global__ __launch_bounds__(256) void gemm_kernel(const float* __restrict__ A,
                                                   const float* __restrict__ W,
                                                   const float* __restrict__ dinv,
                                                   float* __restrict__ out, int n) {
    constexpr int BM = 64, BN = 64, BK = 16;
    __shared__ float As[BK][BM];
    __shared__ float Bs[BK][BN];
    int tid = threadIdx.x;
    int row0 = blockIdx.x * BM;
    int col0 = blockIdx.y * BN;
    int ar = tid >> 2, ak = (tid & 3) * 4;    // A tile load: 64 rows x 16 k
    int br = tid >> 4, bc = (tid & 15) * 4;   // W tile load: 16 k x 64 cols
    int ty = tid >> 4, tx = tid & 15;

    float acc[4][4];
#pragma unroll
    for (int i = 0; i < 4; i++)
#pragma unroll
        for (int j = 0; j < 4; j++) acc[i][j] = 0.f;

    for (int k0 = 0; k0 < K; k0 += BK) {
        float4 av = make_float4(0.f, 0.f, 0.f, 0.f);
        int gr = row0 + ar;
        if (gr < n) av = *(const float4*)(A + (size_t)gr * K + k0 + ak);
        if (RELU) {
            av.x = fmaxf(av.x, 0.f); av.y = fmaxf(av.y, 0.f);
            av.z = fmaxf(av.z, 0.f); av.w = fmaxf(av.w, 0.f);
        }
        As[ak + 0][ar] = av.x; As[ak + 1][ar] = av.y;
        As[ak + 2][ar] = av.z; As[ak + 3][ar] = av.w;
        float4 bv = *(const float4*)(W + (size_t)(k0 + br) * M + col0 + bc);
        *(float4*)(&Bs[br][bc]) = bv;
        __syncthreads();

#pragma unroll
        for (int kk = 0; kk < BK; kk++) {
            float4 a4 = *(const float4*)(&As[kk][ty * 4]);
            float4 b4 = *(const float4*)(&Bs[kk][tx * 4]);
            float a[4] = {a4.x, a4.y, a4.z, a4.w};
            float b[4] = {b4.x, b4.y, b4.z, b4.w};
#pragma unroll
            for (int i = 0; i < 4; i++)
#pragma unroll
                for (int j = 0; j < 4; j++) acc[i][j] += a[i] * b[j];
        }
        __syncthreads();
    }

#pragma unroll
    for (int i = 0; i < 4; i++) {
        int r = row0 + ty * 4 + i;
        if (r < n) {
            float dv = dinv[r];
            float4 o = make_float4(acc[i][0] * dv, acc[i][1] * dv,
                                   acc[i][2] * dv, acc[i][3] * dv);
            *(float4*)(out + (size_t)r * M + col0 + tx * 4) = o;
        }
    }
}

// ---------------- aggregation: out[i] = dinv[i]*(g[i] + sum g[col]) ----------
__global__ __launch_bounds__(256) void agg128_kernel(const float4* __restrict__ g4,
        const int* __restrict__ rowptr, const int* __restrict__ cols,
        const float* __restrict__ dinv, float4* __restrict__ out4, int n) {
    int warp = (blockIdx.x * 256 + threadIdx.x) >> 5;
    int lane = threadIdx.x & 31;
    if (warp >= n) return;
    float4 acc = g4[(size_t)warp * 32 + lane];     // self loop term
    int s = rowptr[warp], e = rowptr[warp + 1];
    for (int base = s; base < e; base += 32) {
        int rem = e - base;
        int myj = (lane < rem) ? cols[base + lane] : 0;
        int cnt = rem < 32 ? rem : 32;
        int t = 0;
        for (; t + 4 <= cnt; t += 4) {
            int j0 = __shfl_sync(0xffffffffu, myj, t);
            int j1 = __shfl_sync(0xffffffffu, myj, t + 1);
            int j2 = __shfl_sync(0xffffffffu, myj, t + 2);
            int j3 = __shfl_sync(0xffffffffu, myj, t + 3);
            float4 v0 = g4[(size_t)j0 * 32 + lane];
            float4 v1 = g4[(size_t)j1 * 32 + lane];
            float4 v2 = g4[(size_t)j2 * 32 + lane];
            float4 v3 = g4[(size_t)j3 * 32 + lane];
            acc.x += v0.x + v1.x + v2.x + v3.x;
            acc.y += v0.y + v1.y + v2.y + v3.y;
            acc.z += v0.z + v1.z + v2.z + v3.z;
            acc.w += v0.w + v1.w + v2.w + v3.w;
        }
        for (; t < cnt; t++) {
            int j = __shfl_sync(0xffffffffu, myj, t);
            float4 v = g4[(size_t)j * 32 + lane];
            acc.x += v.x; acc.y += v.y; acc.z += v.z; acc.w += v.w;
        }
    }
    float dv = dinv[warp];
    acc.x *= dv; acc.y *= dv; acc.z *= dv; acc.w *= dv;
    out4[(size_t)warp * 32 + lane] = acc;
}

__global__ __launch_bounds__(256) void agg64_kernel(const float2* __restrict__ g2,
        const int* __restrict__ rowptr, const int* __restrict__ cols,
        const float* __restrict__ dinv, float2* __restrict__ out2, int n) {
    int warp = (blockIdx.x * 256 + threadIdx.x) >> 5;
    int lane = threadIdx.x & 31;
    if (warp >= n) return;
    float2 acc = g2[(size_t)warp * 32 + lane];
    int s = rowptr[warp], e = rowptr[warp + 1];
    for (int base = s; base < e; base += 32) {
        int rem = e - base;
        int myj = (lane < rem) ? cols[base + lane] : 0;
        int cnt = rem < 32 ? rem : 32;
        int t = 0;
        for (; t + 4 <= cnt; t += 4) {
            int j0 = __shfl_sync(0xffffffffu, myj, t);
            int j1 = __shfl_sync(0xffffffffu, myj, t + 1);
            int j2 = __shfl_sync(0xffffffffu, myj, t + 2);
            int j3 = __shfl_sync(0xffffffffu, myj, t + 3);
            float2 v0 = g2[(size_t)j0 * 32 + lane];
            float2 v1 = g2[(size_t)j1 * 32 + lane];
            float2 v2 = g2[(size_t)j2 * 32 + lane];
            float2 v3 = g2[(size_t)j3 * 32 + lane];
            acc.x += v0.x + v1.x + v2.x + v3.x;
            acc.y += v0.y + v1.y + v2.y + v3.y;
        }
        for (; t < cnt; t++) {
            int j = __shfl_sync(0xffffffffu, myj, t);
            float2 v = g2[(size_t)j * 32 + lane];
            acc.x += v.x; acc.y += v.y;
        }
    }
    float dv = dinv[warp];
    acc.x *= dv; acc.y *= dv;
    out2[(size_t)warp * 32 + lane] = acc;
}

// ---------------- correlation metric -----------------------------------------
template <int D>
__global__ __launch_bounds__(256) void colsum_kernel(const float* __restrict__ h,
                                                     float* __restrict__ cs, int n) {
    __shared__ float sh[256];
    int tid = threadIdx.x;
    int c = tid % D;
    int q = tid / D;
    constexpr int RS = 256 / D;
    float s = 0.f;
    for (int r = blockIdx.x * RS + q; r < n; r += gridDim.x * RS)
        s += h[(size_t)r * D + c];
    sh[tid] = s; __syncthreads();
    if (tid < D) {
#pragma unroll
        for (int k = 1; k < RS; k++) s += sh[tid + k * D];
        atomicAdd(&cs[c], s);
    }
}

template <int D, int TT>   // TT = D/16
__global__ __launch_bounds__(256) void cov_kernel(const float* __restrict__ h,
        const float* __restrict__ cs, float* __restrict__ cov, int n) {
    constexpr int CH = 32;
    __shared__ float sh[CH][D];
    __shared__ float smean[D];
    int tid = threadIdx.x;
    for (int c = tid; c < D; c += 256) smean[c] = cs[c] / (float)n;
    __syncthreads();
    int ty = tid >> 4, tx = tid & 15;
    float acc[TT][TT];
#pragma unroll
    for (int i = 0; i < TT; i++)
#pragma unroll
        for (int j = 0; j < TT; j++) acc[i][j] = 0.f;

    for (int r0 = blockIdx.x * CH; r0 < n; r0 += gridDim.x * CH) {
        int rows = min(CH, n - r0);
        for (int idx = tid; idx < CH * (D / 4); idx += 256) {
            int rr = idx / (D / 4);
            int cc = (idx % (D / 4)) * 4;
            float4 v;
            if (rr < rows) {
                v = *(const float4*)(h + (size_t)(r0 + rr) * D + cc);
                v.x -= smean[cc]; v.y -= smean[cc + 1];
                v.z -= smean[cc + 2]; v.w -= smean[cc + 3];
            } else {
                v = make_float4(0.f, 0.f, 0.f, 0.f);
            }
            *(float4*)(&sh[rr][cc]) = v;
        }
        __syncthreads();
#pragma unroll 4
        for (int r = 0; r < CH; r++) {
            float a[TT], b[TT];
#pragma unroll
            for (int i = 0; i < TT; i += 4) {
                float4 va = *(const float4*)(&sh[r][ty * TT + i]);
                a[i] = va.x; a[i + 1] = va.y; a[i + 2] = va.z; a[i + 3] = va.w;
            }
#pragma unroll
            for (int j = 0; j < TT; j += 4) {
                float4 vb = *(const float4*)(&sh[r][tx * TT + j]);
                b[j] = vb.x; b[j + 1] = vb.y; b[j + 2] = vb.z; b[j + 3] = vb.w;
            }
#pragma unroll
            for (int i = 0; i < TT; i++)
#pragma unroll
                for (int j = 0; j < TT; j++) acc[i][j] += a[i] * b[j];
        }
        __syncthreads();
    }
#pragma unroll
    for (int i = 0; i < TT; i++)
#pragma unroll
        for (int j = 0; j < TT; j++)
            atomicAdd(&cov[(size_t)(ty * TT + i) * D + tx * TT + j], acc[i][j]);
}

template <int D>
__global__ __launch_bounds__(256) void corr_fin_kernel(const float* __restrict__ cov,
                                                       float* __restrict__ outp) {
    __shared__ float sd[D];
    __shared__ float red[256];
    int tid = threadIdx.x;
    for (int c = tid; c < D; c += 256)
        sd[c] = sqrtf(fmaxf(cov[(size_t)c * D + c], 1e-12f));
    __syncthreads();
    float s = 0.f;
    for (int idx = tid; idx < D * D; idx += 256) {
        int i = idx / D, j = idx - i * D;
        if (j > i) s += fabsf(cov[idx]) / (sd[i] * sd[j]);
    }
    red[tid] = s; __syncthreads();
    for (int off = 128; off > 0; off >>= 1) {
        if (tid < off) red[tid] += red[tid + off];
        __syncthreads();
    }
    if (tid == 0) *outp = red[0] / ((float)D * (D - 1) * 0.5f);
}

// ---------------- launch ------------------------------------------------------
extern "C" void kernel_launch(void* const* d_in, const int* in_sizes, int n_in,
                              void* d_out, int out_size) {
    const float* x  = (const float*)d_in[0];
    const int*   ei = (const int*)d_in[1];
    const float* W0 = (const float*)d_in[2];
    const float* W1 = (const float*)d_in[3];
    const float* W2 = (const float*)d_in[4];
    const float* W3 = (const float*)d_in[5];
    float* out = (float*)d_out;

    int n = in_sizes[0] / 256;
    int e = in_sizes[1] / 2;
    if (n > NMAX) n = NMAX;
    if (e > EMAX) e = EMAX;
    const int* row = ei;
    const int* col = ei + e;

    float *g, *h, *dinv, *cs128, *cv128, *cs64, *cv64;
    int *degc, *fill, *rowptr, *bsums, *cols;
    cudaGetSymbolAddress((void**)&g, d_g);
    cudaGetSymbolAddress((void**)&h, d_h);
    cudaGetSymbolAddress((void**)&dinv, d_dinv);
    cudaGetSymbolAddress((void**)&degc, d_degc);
    cudaGetSymbolAddress((void**)&fill, d_fill);
    cudaGetSymbolAddress((void**)&rowptr, d_rowptr);
    cudaGetSymbolAddress((void**)&bsums, d_bsums);
    cudaGetSymbolAddress((void**)&cols, d_cols);
    cudaGetSymbolAddress((void**)&cs128, d_cs128);
    cudaGetSymbolAddress((void**)&cv128, d_cv128);
    cudaGetSymbolAddress((void**)&cs64, d_cs64);
    cudaGetSymbolAddress((void**)&cv64, d_cv64);

    // ---- CSR build (recomputed every call; cheap) ----
    zero_kernel<<<(n + 255) / 256, 256>>>(n);
    hist_kernel<<<(e + 255) / 256, 256>>>(row, degc, e);
    dinv_kernel<<<(n + 255) / 256, 256>>>(degc, dinv, n);
    int nb = (n + 1023) / 1024;
    scan_block_kernel<<<nb, 1024>>>(degc, rowptr, bsums, n);
    scan_sums_kernel<<<1, 1024>>>(bsums, nb);
    scan_add_kernel<<<nb, 1024>>>(rowptr, bsums, n, e);
    scatter_kernel<<<(e + 255) / 256, 256>>>(row, col, rowptr, fill, cols, e);

    dim3 gemm_grid2((n + 63) / 64, 2);
    dim3 gemm_grid1((n + 63) / 64, 1);
    int agg_blocks = (n + 7) / 8;

    // layer 0: x (no relu) -> g -> h1
    gemm_kernel<256, 128, false><<<gemm_grid2, 256>>>(x, W0, dinv, g, n);
    agg128_kernel<<<agg_blocks, 256>>>((const float4*)g, rowptr, cols, dinv, (float4*)h, n);
    // layer 1: relu(h1) -> g -> h2'
    gemm_kernel<128, 128, true><<<gemm_grid2, 256>>>(h, W1, dinv, g, n);
    agg128_kernel<<<agg_blocks, 256>>>((const float4*)g, rowptr, cols, dinv, (float4*)h, n);
    // layer 2: relu -> g -> h3 (pre-relu kept for corr_2)
    gemm_kernel<128, 128, true><<<gemm_grid2, 256>>>(h, W2, dinv, g, n);
    agg128_kernel<<<agg_blocks, 256>>>((const float4*)g, rowptr, cols, dinv, (float4*)h, n);

    // corr_2 on pre-relu layer-2 output (D=128)
    colsum_kernel<128><<<296, 256>>>(h, cs128, n);
    cov_kernel<128, 8><<<296, 256>>>(h, cs128, cv128, n);
    corr_fin_kernel<128><<<1, 256>>>(cv128, out + (size_t)n * 64);

    // layer 3: relu(h3) -> g -> final h (into d_out)
    gemm_kernel<128, 64, true><<<gemm_grid1, 256>>>(h, W3, dinv, g, n);
    agg64_kernel<<<agg_blocks, 256>>>((const float2*)g, rowptr, cols, dinv, (float2*)out, n);

    // corr on final output (D=64)
    colsum_kernel<64><<<296, 256>>>(out, cs64, n);
    cov_kernel<64, 4><<<296, 256>>>(out, cs64, cv64, n);
    corr_fin_kernel<64><<<1, 256>>>(cv64, out + (size_t)n * 64 + 1);
}

// round 5
// speedup vs baseline: 1.1705x; 1.1705x over previous
#include <cuda_runtime.h>
#include <cuda_bf16.h>
#include <cstdint>
#include <cstddef>

#define NMAX 100000
#define EMAX 1600000

// ---------------- scratch (device globals; no allocations allowed) ----------
__device__ float d_g[NMAX * 128];       // dinv * (h @ W)
__device__ float d_h[NMAX * 128];       // aggregated output (pre-relu)
__device__ int   d_degc[NMAX];
__device__ int   d_fill[NMAX];
__device__ float d_dinv[NMAX];
__device__ int   d_rowptr[NMAX + 1];
__device__ int   d_bsums[1024];
__device__ int   d_cols[EMAX];
__device__ float d_cs128[128];
__device__ float d_cv128[128 * 128];
__device__ float d_cs64[64];
__device__ float d_cv64[64 * 64];
__device__ uint32_t d_Bhi[256 * 128 / 2];   // B-fragment image (hi words)
__device__ uint32_t d_Blo[256 * 128 / 2];   // B-fragment image (lo words)

// ---------------- init -------------------------------------------------------
__global__ void zero_kernel(int n) {
    int i = blockIdx.x * blockDim.x + threadIdx.x;
    if (i < n) { d_degc[i] = 0; d_fill[i] = 0; }
    if (i < 128) d_cs128[i] = 0.f;
    if (i < 64)  d_cs64[i] = 0.f;
    if (i < 128 * 128) d_cv128[i] = 0.f;
    if (i < 64 * 64)   d_cv64[i] = 0.f;
}

__global__ void hist_kernel(const int* __restrict__ row, int* __restrict__ degc, int e) {
    int i = blockIdx.x * blockDim.x + threadIdx.x;
    if (i < e) atomicAdd(&degc[row[i]], 1);
}

__global__ void dinv_kernel(const int* __restrict__ degc, float* __restrict__ dinv, int n) {
    int i = blockIdx.x * blockDim.x + threadIdx.x;
    if (i < n) dinv[i] = rsqrtf((float)(degc[i] + 1));   // +1 self loop, always > 0
}

// ---------------- exclusive scan (rowptr) -----------------------------------
__global__ void scan_block_kernel(const int* __restrict__ cnt, int* __restrict__ excl,
                                  int* __restrict__ bsums, int n) {
    __shared__ int sh[1024];
    int tid = threadIdx.x;
    int i = blockIdx.x * 1024 + tid;
    int v = (i < n) ? cnt[i] : 0;
    sh[tid] = v; __syncthreads();
    for (int off = 1; off < 1024; off <<= 1) {
        int t = (tid >= off) ? sh[tid - off] : 0;
        __syncthreads();
        sh[tid] += t;
        __syncthreads();
    }
    if (i < n) excl[i] = sh[tid] - v;
    if (tid == 1023) bsums[blockIdx.x] = sh[tid];
}

__global__ void scan_sums_kernel(int* __restrict__ bsums, int nb) {
    __shared__ int sh[1024];
    int tid = threadIdx.x;
    int v = (tid < nb) ? bsums[tid] : 0;
    sh[tid] = v; __syncthreads();
    for (int off = 1; off < 1024; off <<= 1) {
        int t = (tid >= off) ? sh[tid - off] : 0;
        __syncthreads();
        sh[tid] += t;
        __syncthreads();
    }
    if (tid < nb) bsums[tid] = sh[tid] - v;
}

__global__ void scan_add_kernel(int* __restrict__ rowptr, const int* __restrict__ bsums,
                                int n, int e) {
    int i = blockIdx.x * 1024 + threadIdx.x;
    if (i < n) rowptr[i] += bsums[blockIdx.x];
    if (blockIdx.x == 0 && threadIdx.x == 0) rowptr[n] = e;
}

__global__ void scatter_kernel(const int* __restrict__ row, const int* __restrict__ col,
                               const int* __restrict__ rowptr, int* __restrict__ fill,
                               int* __restrict__ colsorted, int e) {
    int i = blockIdx.x * blockDim.x + threadIdx.x;
    if (i < e) {
        int r = row[i];
        int pos = rowptr[r] + atomicAdd(&fill[r], 1);
        colsorted[pos] = col[i];
    }
}

// ---------------- helpers ----------------------------------------------------
__device__ __forceinline__ uint32_t pack_hi(float a, float b, uint32_t& lo) {
    __nv_bfloat16 h0 = __float2bfloat16(a);
    __nv_bfloat16 h1 = __float2bfloat16(b);
    __nv_bfloat16 l0 = __float2bfloat16(a - __bfloat162float(h0));
    __nv_bfloat16 l1 = __float2bfloat16(b - __bfloat162float(h1));
    lo = (uint32_t)__bfloat16_as_ushort(l0) | ((uint32_t)__bfloat16_as_ushort(l1) << 16);
    return (uint32_t)__bfloat16_as_ushort(h0) | ((uint32_t)__bfloat16_as_ushort(h1) << 16);
}

__device__ __forceinline__ void mma16816(float* c, const uint32_t* a,
                                         uint32_t b0, uint32_t b1) {
    asm volatile("mma.sync.aligned.m16n8k16.row.col.f32.bf16.bf16.f32 "
                 "{%0,%1,%2,%3}, {%4,%5,%6,%7}, {%8,%9}, {%0,%1,%2,%3};"
                 : "+f"(c[0]), "+f"(c[1]), "+f"(c[2]), "+f"(c[3])
                 : "r"(a[0]), "r"(a[1]), "r"(a[2]), "r"(a[3]), "r"(b0), "r"(b1));
}

// ---------------- weight prep: W[K][N] -> HMMA B-fragment images -------------
// entry = (s*NT + j)*32 + lane covers (k = s*16 + (lane%4)*2 (+1,+8,+9), n = j*8 + lane/4)
template <int K, int N>
__global__ void wprep_kernel(const float* __restrict__ W,
                             uint32_t* __restrict__ hi, uint32_t* __restrict__ lo) {
    constexpr int NT = N / 8;
    int entry = blockIdx.x * 256 + threadIdx.x;
    if (entry >= (K / 16) * NT * 32) return;
    int lane = entry & 31;
    int j = (entry >> 5) % NT;
    int s = entry / (32 * NT);
    int k0 = s * 16 + (lane & 3) * 2;
    int nn = j * 8 + (lane >> 2);
    uint32_t l0, l1;
    uint32_t h0 = pack_hi(W[(size_t)k0 * N + nn],       W[(size_t)(k0 + 1) * N + nn], l0);
    uint32_t h1 = pack_hi(W[(size_t)(k0 + 8) * N + nn], W[(size_t)(k0 + 9) * N + nn], l1);
    hi[entry * 2 + 0] = h0; hi[entry * 2 + 1] = h1;
    lo[entry * 2 + 0] = l0; lo[entry * 2 + 1] = l1;
}

// ---------------- tensor GEMM: out = dinv * (act(A) @ W) ---------------------
// 8 warps/CTA, 16 rows/warp, 128 rows/CTA. split-bf16 3-MMA fp32 emulation.
template <int K, int N, bool RELU>
__global__ __launch_bounds__(256) void gemm_mma_kernel(
        const float* __restrict__ A,
        const uint32_t* __restrict__ Bhi, const uint32_t* __restrict__ Blo,
        const float* __restrict__ dinv, float* __restrict__ out, int n)
{
    constexpr int NT = N / 8, KS = K / 16;
    int tid = threadIdx.x;
    int w = tid >> 5, lane = tid & 31;
    int g = lane >> 2, t = lane & 3;
    int r0 = blockIdx.x * 128 + w * 16 + g;
    int r1 = r0 + 8;
    bool v0 = r0 < n, v1 = r1 < n;

    float acc[NT][4];
#pragma unroll
    for (int j = 0; j < NT; j++)
#pragma unroll
        for (int q = 0; q < 4; q++) acc[j][q] = 0.f;

    const float* A0 = A + (size_t)r0 * K + t * 2;
    const float* A1 = A + (size_t)r1 * K + t * 2;

    for (int s = 0; s < KS; s++) {
        int kb = s * 16;
        float2 z = make_float2(0.f, 0.f);
        float2 p00 = v0 ? *(const float2*)(A0 + kb)     : z;
        float2 p01 = v0 ? *(const float2*)(A0 + kb + 8) : z;
        float2 p10 = v1 ? *(const float2*)(A1 + kb)     : z;
        float2 p11 = v1 ? *(const float2*)(A1 + kb + 8) : z;
        if (RELU) {
            p00.x = fmaxf(p00.x, 0.f); p00.y = fmaxf(p00.y, 0.f);
            p01.x = fmaxf(p01.x, 0.f); p01.y = fmaxf(p01.y, 0.f);
            p10.x = fmaxf(p10.x, 0.f); p10.y = fmaxf(p10.y, 0.f);
            p11.x = fmaxf(p11.x, 0.f); p11.y = fmaxf(p11.y, 0.f);
        }
        uint32_t ahi[4], alo[4];
        ahi[0] = pack_hi(p00.x, p00.y, alo[0]);   // (row g,   k, k+1)
        ahi[1] = pack_hi(p10.x, p10.y, alo[1]);   // (row g+8, k, k+1)
        ahi[2] = pack_hi(p01.x, p01.y, alo[2]);   // (row g,   k+8, k+9)
        ahi[3] = pack_hi(p11.x, p11.y, alo[3]);   // (row g+8, k+8, k+9)

        const uint32_t* bh = Bhi + (size_t)s * NT * 64 + lane * 2;
        const uint32_t* bl = Blo + (size_t)s * NT * 64 + lane * 2;
#pragma unroll
        for (int j = 0; j < NT; j++) {
            uint32_t b0h = bh[j * 64], b1h = bh[j * 64 + 1];
            uint32_t b0l = bl[j * 64], b1l = bl[j * 64 + 1];
            mma16816(acc[j], ahi, b0h, b1h);
            mma16816(acc[j], ahi, b0l, b1l);
            mma16816(acc[j], alo, b0h, b1h);
        }
    }

    float dv0 = v0 ? dinv[r0] : 0.f;
    float dv1 = v1 ? dinv[r1] : 0.f;
#pragma unroll
    for (int j = 0; j < NT; j++) {
        int c = j * 8 + t * 2;
        if (v0) *(float2*)(out + (size_t)r0 * N + c) =
            make_float2(acc[j][0] * dv0, acc[j][1] * dv0);
        if (v1) *(float2*)(out + (size_t)r1 * N + c) =
            make_float2(acc[j][2] * dv1, acc[j][3] * dv1);
    }
}

// ---------------- aggregation: out[i] = dinv[i]*(g[i] + sum g[col]) ----------
__global__ __launch_bounds__(256) void agg128_kernel(const float4* __restrict__ g4,
        const int* __restrict__ rowptr, const int* __restrict__ cols,
        const float* __restrict__ dinv, float4* __restrict__ out4, int n) {
    int warp = (blockIdx.x * 256 + threadIdx.x) >> 5;
    int lane = threadIdx.x & 31;
    if (warp >= n) return;
    float4 acc = g4[(size_t)warp * 32 + lane];
    int s = rowptr[warp], e = rowptr[warp + 1];
    for (int base = s; base < e; base += 32) {
        int rem = e - base;
        int myj = (lane < rem) ? cols[base + lane] : 0;
        int cnt = rem < 32 ? rem : 32;
        int t = 0;
        for (; t + 4 <= cnt; t += 4) {
            int j0 = __shfl_sync(0xffffffffu, myj, t);
            int j1 = __shfl_sync(0xffffffffu, myj, t + 1);
            int j2 = __shfl_sync(0xffffffffu, myj, t + 2);
            int j3 = __shfl_sync(0xffffffffu, myj, t + 3);
            float4 v0 = g4[(size_t)j0 * 32 + lane];
            float4 v1 = g4[(size_t)j1 * 32 + lane];
            float4 v2 = g4[(size_t)j2 * 32 + lane];
            float4 v3 = g4[(size_t)j3 * 32 + lane];
            acc.x += v0.x + v1.x + v2.x + v3.x;
            acc.y += v0.y + v1.y + v2.y + v3.y;
            acc.z += v0.z + v1.z + v2.z + v3.z;
            acc.w += v0.w + v1.w + v2.w + v3.w;
        }
        for (; t < cnt; t++) {
            int j = __shfl_sync(0xffffffffu, myj, t);
            float4 v = g4[(size_t)j * 32 + lane];
            acc.x += v.x; acc.y += v.y; acc.z += v.z; acc.w += v.w;
        }
    }
    float dv = dinv[warp];
    acc.x *= dv; acc.y *= dv; acc.z *= dv; acc.w *= dv;
    out4[(size_t)warp * 32 + lane] = acc;
}

__global__ __launch_bounds__(256) void agg64_kernel(const float2* __restrict__ g2,
        const int* __restrict__ rowptr, const int* __restrict__ cols,
        const float* __restrict__ dinv, float2* __restrict__ out2, int n) {
    int warp = (blockIdx.x * 256 + threadIdx.x) >> 5;
    int lane = threadIdx.x & 31;
    if (warp >= n) return;
    float2 acc = g2[(size_t)warp * 32 + lane];
    int s = rowptr[warp], e = rowptr[warp + 1];
    for (int base = s; base < e; base += 32) {
        int rem = e - base;
        int myj = (lane < rem) ? cols[base + lane] : 0;
        int cnt = rem < 32 ? rem : 32;
        int t = 0;
        for (; t + 4 <= cnt; t += 4) {
            int j0 = __shfl_sync(0xffffffffu, myj, t);
            int j1 = __shfl_sync(0xffffffffu, myj, t + 1);
            int j2 = __shfl_sync(0xffffffffu, myj, t + 2);
            int j3 = __shfl_sync(0xffffffffu, myj, t + 3);
            float2 v0 = g2[(size_t)j0 * 32 + lane];
            float2 v1 = g2[(size_t)j1 * 32 + lane];
            float2 v2 = g2[(size_t)j2 * 32 + lane];
            float2 v3 = g2[(size_t)j3 * 32 + lane];
            acc.x += v0.x + v1.x + v2.x + v3.x;
            acc.y += v0.y + v1.y + v2.y + v3.y;
        }
        for (; t < cnt; t++) {
            int j = __shfl_sync(0xffffffffu, myj, t);
            float2 v = g2[(size_t)j * 32 + lane];
            acc.x += v.x; acc.y += v.y;
        }
    }
    float dv = dinv[warp];
    acc.x *= dv; acc.y *= dv;
    out2[(size_t)warp * 32 + lane] = acc;
}

// ---------------- correlation metric -----------------------------------------
template <int D>
__global__ __launch_bounds__(256) void colsum_kernel(const float* __restrict__ h,
                                                     float* __restrict__ cs, int n) {
    __shared__ float sh[256];
    int tid = threadIdx.x;
    int c = tid % D;
    int q = tid / D;
    constexpr int RS = 256 / D;
    float s = 0.f;
    for (int r = blockIdx.x * RS + q; r < n; r += gridDim.x * RS)
        s += h[(size_t)r * D + c];
    sh[tid] = s; __syncthreads();
    if (tid < D) {
#pragma unroll
        for (int k = 1; k < RS; k++) s += sh[tid + k * D];
        atomicAdd(&cs[c], s);
    }
}

template <int D, int TT>   // TT = D/16
__global__ __launch_bounds__(256) void cov_kernel(const float* __restrict__ h,
        const float* __restrict__ cs, float* __restrict__ cov, int n) {
    constexpr int CH = 32;
    __shared__ float sh[CH][D];
    __shared__ float smean[D];
    int tid = threadIdx.x;
    for (int c = tid; c < D; c += 256) smean[c] = cs[c] / (float)n;
    __syncthreads();
    int ty = tid >> 4, tx = tid & 15;
    float acc[TT][TT];
#pragma unroll
    for (int i = 0; i < TT; i++)
#pragma unroll
        for (int j = 0; j < TT; j++) acc[i][j] = 0.f;

    for (int r0 = blockIdx.x * CH; r0 < n; r0 += gridDim.x * CH) {
        int rows = min(CH, n - r0);
        for (int idx = tid; idx < CH * (D / 4); idx += 256) {
            int rr = idx / (D / 4);
            int cc = (idx % (D / 4)) * 4;
            float4 v;
            if (rr < rows) {
                v = *(const float4*)(h + (size_t)(r0 + rr) * D + cc);
                v.x -= smean[cc]; v.y -= smean[cc + 1];
                v.z -= smean[cc + 2]; v.w -= smean[cc + 3];
            } else {
                v = make_float4(0.f, 0.f, 0.f, 0.f);
            }
            *(float4*)(&sh[rr][cc]) = v;
        }
        __syncthreads();
#pragma unroll 4
        for (int r = 0; r < CH; r++) {
            float a[TT], b[TT];
#pragma unroll
            for (int i = 0; i < TT; i += 4) {
                float4 va = *(const float4*)(&sh[r][ty * TT + i]);
                a[i] = va.x; a[i + 1] = va.y; a[i + 2] = va.z; a[i + 3] = va.w;
            }
#pragma unroll
            for (int j = 0; j < TT; j += 4) {
                float4 vb = *(const float4*)(&sh[r][tx * TT + j]);
                b[j] = vb.x; b[j + 1] = vb.y; b[j + 2] = vb.z; b[j + 3] = vb.w;
            }
#pragma unroll
            for (int i = 0; i < TT; i++)
#pragma unroll
                for (int j = 0; j < TT; j++) acc[i][j] += a[i] * b[j];
        }
        __syncthreads();
    }
#pragma unroll
    for (int i = 0; i < TT; i++)
#pragma unroll
        for (int j = 0; j < TT; j++)
            atomicAdd(&cov[(size_t)(ty * TT + i) * D + tx * TT + j], acc[i][j]);
}

template <int D>
__global__ __launch_bounds__(256) void corr_fin_kernel(const float* __restrict__ cov,
                                                       float* __restrict__ outp) {
    __shared__ float sd[D];
    __shared__ float red[256];
    int tid = threadIdx.x;
    for (int c = tid; c < D; c += 256)
        sd[c] = sqrtf(fmaxf(cov[(size_t)c * D + c], 1e-12f));
    __syncthreads();
    float s = 0.f;
    for (int idx = tid; idx < D * D; idx += 256) {
        int i = idx / D, j = idx - i * D;
        if (j > i) s += fabsf(cov[idx]) / (sd[i] * sd[j]);
    }
    red[tid] = s; __syncthreads();
    for (int off = 128; off > 0; off >>= 1) {
        if (tid < off) red[tid] += red[tid + off];
        __syncthreads();
    }
    if (tid == 0) *outp = red[0] / ((float)D * (D - 1) * 0.5f);
}

// ---------------- launch ------------------------------------------------------
extern "C" void kernel_launch(void* const* d_in, const int* in_sizes, int n_in,
                              void* d_out, int out_size) {
    const float* x  = (const float*)d_in[0];
    const int*   ei = (const int*)d_in[1];
    const float* W0 = (const float*)d_in[2];
    const float* W1 = (const float*)d_in[3];
    const float* W2 = (const float*)d_in[4];
    const float* W3 = (const float*)d_in[5];
    float* out = (float*)d_out;

    int n = in_sizes[0] / 256;
    int e = in_sizes[1] / 2;
    if (n > NMAX) n = NMAX;
    if (e > EMAX) e = EMAX;
    const int* row = ei;
    const int* col = ei + e;

    float *g, *h, *dinv, *cs128, *cv128, *cs64, *cv64;
    int *degc, *fill, *rowptr, *bsums, *cols;
    uint32_t *bhi, *blo;
    cudaGetSymbolAddress((void**)&g, d_g);
    cudaGetSymbolAddress((void**)&h, d_h);
    cudaGetSymbolAddress((void**)&dinv, d_dinv);
    cudaGetSymbolAddress((void**)&degc, d_degc);
    cudaGetSymbolAddress((void**)&fill, d_fill);
    cudaGetSymbolAddress((void**)&rowptr, d_rowptr);
    cudaGetSymbolAddress((void**)&bsums, d_bsums);
    cudaGetSymbolAddress((void**)&cols, d_cols);
    cudaGetSymbolAddress((void**)&cs128, d_cs128);
    cudaGetSymbolAddress((void**)&cv128, d_cv128);
    cudaGetSymbolAddress((void**)&cs64, d_cs64);
    cudaGetSymbolAddress((void**)&cv64, d_cv64);
    cudaGetSymbolAddress((void**)&bhi, d_Bhi);
    cudaGetSymbolAddress((void**)&blo, d_Blo);

    // ---- CSR build ----
    zero_kernel<<<(n + 255) / 256, 256>>>(n);
    hist_kernel<<<(e + 255) / 256, 256>>>(row, degc, e);
    dinv_kernel<<<(n + 255) / 256, 256>>>(degc, dinv, n);
    int nb = (n + 1023) / 1024;
    scan_block_kernel<<<nb, 1024>>>(degc, rowptr, bsums, n);
    scan_sums_kernel<<<1, 1024>>>(bsums, nb);
    scan_add_kernel<<<nb, 1024>>>(rowptr, bsums, n, e);
    scatter_kernel<<<(e + 255) / 256, 256>>>(row, col, rowptr, fill, cols, e);

    int gemm_blocks = (n + 127) / 128;
    int agg_blocks = (n + 7) / 8;

    // layer 0: x (no relu) -> g -> h1
    wprep_kernel<256, 128><<<(256 * 128 / 4 + 255) / 256, 256>>>(W0, bhi, blo);
    gemm_mma_kernel<256, 128, false><<<gemm_blocks, 256>>>(x, bhi, blo, dinv, g, n);
    agg128_kernel<<<agg_blocks, 256>>>((const float4*)g, rowptr, cols, dinv, (float4*)h, n);
    // layer 1
    wprep_kernel<128, 128><<<(128 * 128 / 4 + 255) / 256, 256>>>(W1, bhi, blo);
    gemm_mma_kernel<128, 128, true><<<gemm_blocks, 256>>>(h, bhi, blo, dinv, g, n);
    agg128_kernel<<<agg_blocks, 256>>>((const float4*)g, rowptr, cols, dinv, (float4*)h, n);
    // layer 2
    wprep_kernel<128, 128><<<(128 * 128 / 4 + 255) / 256, 256>>>(W2, bhi, blo);
    gemm_mma_kernel<128, 128, true><<<gemm_blocks, 256>>>(h, bhi, blo, dinv, g, n);
    agg128_kernel<<<agg_blocks, 256>>>((const float4*)g, rowptr, cols, dinv, (float4*)h, n);

    // corr_2 on pre-relu layer-2 output (D=128)
    colsum_kernel<128><<<296, 256>>>(h, cs128, n);
    cov_kernel<128, 8><<<296, 256>>>(h, cs128, cv128, n);
    corr_fin_kernel<128><<<1, 256>>>(cv128, out + (size_t)n * 64);

    // layer 3
    wprep_kernel<128, 64><<<(128 * 64 / 4 + 255) / 256, 256>>>(W3, bhi, blo);
    gemm_mma_kernel<128, 64, true><<<gemm_blocks, 256>>>(h, bhi, blo, dinv, g, n);
    agg64_kernel<<<agg_blocks, 256>>>((const float2*)g, rowptr, cols, dinv, (float2*)out, n);

    // corr on final output (D=64)
    colsum_kernel<64><<<296, 256>>>(out, cs64, n);
    cov_kernel<64, 4><<<296, 256>>>(out, cs64, cv64, n);
    corr_fin_kernel<64><<<1, 256>>>(cv64, out + (size_t)n * 64 + 1);
}